// round 13
// baseline (speedup 1.0000x reference)
#include <cuda_runtime.h>
#include <cuda_fp16.h>
#include <math.h>
#include <stdint.h>

#define D      128
#define TILE   128
#define NTHR   512
#define MAXN   51200

// ---------------------------------------------------------------------------
// Static device scratch (no cudaMalloc allowed)
// ---------------------------------------------------------------------------
__device__ float    g_agg[(size_t)MAXN * D];   // scatter-add target
__device__ uint32_t g_Bh[4][8192];             // fp16 W images, uint4-packed frag order
// 0 = We1, 1 = We2, 2 = Wu1, 3 = Wu2  (32 KB each)

__device__ __forceinline__ uint32_t h2pack(float lo, float hi) {
    __half2 h = __floats2half2_rn(lo, hi);
    return *reinterpret_cast<uint32_t*>(&h);
}

__device__ __forceinline__ float gelu_exact(float v) {
    return 0.5f * v * (1.0f + erff(v * 0.70710678118654752f));
}

__device__ __forceinline__ void mma_f16(float* c,
                                        uint32_t a0, uint32_t a1, uint32_t a2, uint32_t a3,
                                        uint32_t b0, uint32_t b1) {
    asm volatile(
        "mma.sync.aligned.m16n8k16.row.col.f32.f16.f16.f32 "
        "{%0,%1,%2,%3}, {%4,%5,%6,%7}, {%8,%9}, {%0,%1,%2,%3};"
        : "+f"(c[0]), "+f"(c[1]), "+f"(c[2]), "+f"(c[3])
        : "r"(a0), "r"(a1), "r"(a2), "r"(a3), "r"(b0), "r"(b1));
}

__device__ __forceinline__ void red_add_v4(float* p, float4 v) {
    asm volatile("red.global.add.v4.f32 [%0], {%1,%2,%3,%4};"
                 :: "l"(p), "f"(v.x), "f"(v.y), "f"(v.z), "f"(v.w) : "memory");
}

// ---------------------------------------------------------------------------
// prep: W[k][n] -> fp16 m16n8k16 B-fragment order, uint4-packed.
// ---------------------------------------------------------------------------
__global__ void prep_weights(const float* __restrict__ We1, const float* __restrict__ We2,
                             const float* __restrict__ Wu1, const float* __restrict__ Wu2)
{
    int id = blockIdx.x * blockDim.x + threadIdx.x;
    if (id >= 4 * 4096) return;
    int m = id >> 12, r = id & 4095;
    int ca = r >> 8, s = (r >> 5) & 7, lane = r & 31;
    int g = lane >> 2, t = lane & 3;
    const float* W = (m == 0) ? We1 : (m == 1) ? We2 : (m == 2) ? Wu1 : Wu2;
    int n = ca * 8 + g;
    int k0 = 16 * s + 2 * t;
    uint32_t b0 = h2pack(W[k0 * D + n],       W[(k0 + 1) * D + n]);
    uint32_t b1 = h2pack(W[(k0 + 8) * D + n], W[(k0 + 9) * D + n]);
    int idx = ((ca * 4 + (s >> 1)) * 32 + lane) * 4 + (s & 1) * 2;
    g_Bh[m][idx]     = b0;
    g_Bh[m][idx + 1] = b1;
}

__global__ void zero_agg(size_t nd)
{
    size_t i = ((size_t)blockIdx.x * blockDim.x + threadIdx.x) * 4;
    size_t stride = (size_t)gridDim.x * blockDim.x * 4;
    float4 z = make_float4(0.f, 0.f, 0.f, 0.f);
    for (; i < nd; i += stride) *(float4*)(g_agg + i) = z;
}

// ---------------------------------------------------------------------------
// 32(rows)x32(cols)x128 GEMM slice per warp (fp16, m16n8k16);
// A fragment-major smem (LDS.128), B uint4 frags from L1-resident global.
// ra0 = row-group*2 (2 row atoms); Bq = image_u4 + wn*512 + lane.
// ---------------------------------------------------------------------------
__device__ __forceinline__ void do_gemm(const uint4* __restrict__ F,
                                        const uint4* __restrict__ Bq,
                                        int ra0, int lane,
                                        float acc[2][4][4])
{
    #pragma unroll
    for (int r = 0; r < 2; ++r)
        #pragma unroll
        for (int ca = 0; ca < 4; ++ca)
            #pragma unroll
            for (int q = 0; q < 4; ++q) acc[r][ca][q] = 0.f;

    #pragma unroll
    for (int sp = 0; sp < 4; ++sp) {
        int s0 = sp * 2, s1 = s0 + 1;
        uint4 a0[2], a1[2];
        #pragma unroll
        for (int r = 0; r < 2; ++r) {
            a0[r] = F[((ra0 + r) * 8 + s0) * 33 + lane];
            a1[r] = F[((ra0 + r) * 8 + s1) * 33 + lane];
        }
        #pragma unroll
        for (int ca = 0; ca < 4; ++ca) {
            uint4 b = __ldg(Bq + (ca * 4 + sp) * 32);
            #pragma unroll
            for (int r = 0; r < 2; ++r) {
                mma_f16(acc[r][ca], a0[r].x, a0[r].y, a0[r].z, a0[r].w, b.x, b.y);
                mma_f16(acc[r][ca], a1[r].x, a1[r].y, a1[r].z, a1[r].w, b.z, b.w);
            }
        }
    }
}

// ---------------------------------------------------------------------------
// Fused 2-layer MLP on a 128-row tile (fp16 MMA). 16 warps: 4 row-groups
// (32 rows) x 4 col-groups (32 cols); acc = 32 regs/thread -> 64-reg budget
// -> 2 CTAs x 512 thr = 32 warps/SM (2x occupancy of the 256-thr version).
// smem = A-frag (33.8KB) + H-frag (33.8KB), overlaid by 128x132 fp32 region.
// ---------------------------------------------------------------------------
template <bool EDGE>
__global__ void __launch_bounds__(NTHR, 2) fused_mlp_mma(
    const float* __restrict__ x,
    const int*   __restrict__ src,
    const int*   __restrict__ dst,
    const float* __restrict__ ea,
    const float* __restrict__ b1,
    const float* __restrict__ b2,
    const float* __restrict__ eps,
    float*       __restrict__ out,
    int count)
{
    extern __shared__ float Asf[];                 // 16896 floats = 4224 uint4
    uint4* As4 = (uint4*)Asf;                      // A frags: [0, 2112)
    uint4* Hs4 = As4 + 2112;                       // H frags: [2112, 4224)

    const int tid  = threadIdx.x;
    const int lane = tid & 31, wid = tid >> 5;
    const int wm = wid & 3, wn = wid >> 2;         // 4 row-groups x 4 col-groups
    const int g = lane >> 2, t = lane & 3;
    const int r0 = blockIdx.x * TILE;
    const int imgbase = EDGE ? 0 : 2;

    // ---- gather: thread (atom = tid>>6, g_g = (tid>>3)&7, s = tid&7)
    //      handles rows (atom*16+g_g, +8), cols [16s, 16s+16) ----
    {
        const int atom = tid >> 6;
        const int g_g  = (tid >> 3) & 7;
        const int s    = tid & 7;
        const int rowA = r0 + atom * 16 + g_g, rowB = rowA + 8;
        const bool vA = rowA < count, vB = rowB < count;

        const float *pxA = nullptr, *peA = nullptr, *pxB = nullptr, *peB = nullptr;
        float oe = 0.f;
        if (EDGE) {
            if (vA) { pxA = x + (size_t)__ldg(&src[rowA]) * D; peA = ea + (size_t)rowA * D; }
            if (vB) { pxB = x + (size_t)__ldg(&src[rowB]) * D; peB = ea + (size_t)rowB * D; }
        } else {
            oe = 1.0f + eps[0];
            if (vA) { pxA = x + (size_t)rowA * D; peA = g_agg + (size_t)rowA * D; }
            if (vB) { pxB = x + (size_t)rowB * D; peB = g_agg + (size_t)rowB * D; }
        }

        float vAr[16], vBr[16];
        #pragma unroll
        for (int i = 0; i < 16; ++i) { vAr[i] = 0.f; vBr[i] = 0.f; }
        if (vA) {
            #pragma unroll
            for (int c = 0; c < 4; ++c) {
                float4 xa  = __ldg((const float4*)(pxA + s * 16 + c * 4));
                float4 eaa = __ldg((const float4*)(peA + s * 16 + c * 4));
                if (EDGE) {
                    vAr[c*4+0] = xa.x + eaa.x; vAr[c*4+1] = xa.y + eaa.y;
                    vAr[c*4+2] = xa.z + eaa.z; vAr[c*4+3] = xa.w + eaa.w;
                } else {
                    vAr[c*4+0] = fmaf(oe, xa.x, eaa.x); vAr[c*4+1] = fmaf(oe, xa.y, eaa.y);
                    vAr[c*4+2] = fmaf(oe, xa.z, eaa.z); vAr[c*4+3] = fmaf(oe, xa.w, eaa.w);
                }
            }
        }
        if (vB) {
            #pragma unroll
            for (int c = 0; c < 4; ++c) {
                float4 xa  = __ldg((const float4*)(pxB + s * 16 + c * 4));
                float4 eaa = __ldg((const float4*)(peB + s * 16 + c * 4));
                if (EDGE) {
                    vBr[c*4+0] = xa.x + eaa.x; vBr[c*4+1] = xa.y + eaa.y;
                    vBr[c*4+2] = xa.z + eaa.z; vBr[c*4+3] = xa.w + eaa.w;
                } else {
                    vBr[c*4+0] = fmaf(oe, xa.x, eaa.x); vBr[c*4+1] = fmaf(oe, xa.y, eaa.y);
                    vBr[c*4+2] = fmaf(oe, xa.z, eaa.z); vBr[c*4+3] = fmaf(oe, xa.w, eaa.w);
                }
            }
        }
        uint32_t base = (uint32_t)(atom * 8 + s) * 33 + g_g * 4;
        #pragma unroll
        for (int tt = 0; tt < 4; ++tt) {
            As4[base + tt] = make_uint4(
                h2pack(vAr[2*tt],     vAr[2*tt + 1]),
                h2pack(vBr[2*tt],     vBr[2*tt + 1]),
                h2pack(vAr[8 + 2*tt], vAr[9 + 2*tt]),
                h2pack(vBr[8 + 2*tt], vBr[9 + 2*tt]));
        }
    }
    __syncthreads();

    const uint4* Bq1 = (const uint4*)&g_Bh[imgbase][0]     + wn * 512 + lane;
    const uint4* Bq2 = (const uint4*)&g_Bh[imgbase + 1][0] + wn * 512 + lane;
    const int ra0 = wm * 2;

    float acc[2][4][4];

    // ---- GEMM1 (reads As4) ----
    do_gemm(As4, Bq1, ra0, lane, acc);
    // NO sync: H goes to its own buffer.

    // ---- epilogue1: H = GELU(C + b1) -> Hs4 ----
    #pragma unroll
    for (int p = 0; p < 2; ++p) {
        int sH = wn * 2 + p;
        int ca0 = 2 * p, ca1 = 2 * p + 1;
        int cb0 = wn * 32 + ca0 * 8 + 2 * t;
        int cb1 = wn * 32 + ca1 * 8 + 2 * t;
        float b00 = __ldg(&b1[cb0]), b01 = __ldg(&b1[cb0 + 1]);
        float b10 = __ldg(&b1[cb1]), b11 = __ldg(&b1[cb1 + 1]);
        #pragma unroll
        for (int ma = 0; ma < 2; ++ma) {
            uint4 f;
            f.x = h2pack(gelu_exact(acc[ma][ca0][0] + b00), gelu_exact(acc[ma][ca0][1] + b01));
            f.y = h2pack(gelu_exact(acc[ma][ca0][2] + b00), gelu_exact(acc[ma][ca0][3] + b01));
            f.z = h2pack(gelu_exact(acc[ma][ca1][0] + b10), gelu_exact(acc[ma][ca1][1] + b11));
            f.w = h2pack(gelu_exact(acc[ma][ca1][2] + b10), gelu_exact(acc[ma][ca1][3] + b11));
            Hs4[((ra0 + ma) * 8 + sH) * 33 + lane] = f;
        }
    }
    __syncthreads();

    // ---- GEMM2 (reads Hs4) ----
    do_gemm(Hs4, Bq2, ra0, lane, acc);
    __syncthreads();     // H reads complete before linear overlay writes

    // ---- epilogue2: raw C2 -> linear smem (fp32 overlays frag buffers) ----
    #pragma unroll
    for (int ca = 0; ca < 4; ++ca) {
        int col = wn * 32 + ca * 8 + 2 * t;
        #pragma unroll
        for (int ma = 0; ma < 2; ++ma) {
            int row = wm * 32 + ma * 16 + g;
            *(float2*)(Asf + row * 132 + col)       = make_float2(acc[ma][ca][0], acc[ma][ca][1]);
            *(float2*)(Asf + (row + 8) * 132 + col) = make_float2(acc[ma][ca][2], acc[ma][ca][3]);
        }
    }
    __syncthreads();

    // ---- output: coalesced + bias; edge -> red.v4 scatter, node -> store ----
    {
        int c4 = lane * 4;
        float4 bias = *(const float4*)&b2[c4];
        int rbase = wid * 8;
        #pragma unroll
        for (int i = 0; i < 8; ++i) {
            int r = rbase + i;
            int row = r0 + r;
            if (row < count) {
                float4 v = *(float4*)(Asf + r * 132 + c4);
                v.x += bias.x; v.y += bias.y; v.z += bias.z; v.w += bias.w;
                if (EDGE) {
                    int dn = __ldg(&dst[row]);
                    red_add_v4(g_agg + (size_t)dn * D + c4, v);
                } else {
                    *(float4*)(out + (size_t)row * D + c4) = v;
                }
            }
        }
    }
}

// ---------------------------------------------------------------------------
// Inputs: x, edge_index(int32 [2,E]), edge_attr, We1, be1, We2, be2,
//         Wu1, bu1, Wu2, bu2, eps
// ---------------------------------------------------------------------------
extern "C" void kernel_launch(void* const* d_in, const int* in_sizes, int n_in,
                              void* d_out, int out_size)
{
    const float* x   = (const float*)d_in[0];
    const int*   ei  = (const int*)d_in[1];
    const float* ea  = (const float*)d_in[2];
    const float* We1 = (const float*)d_in[3];
    const float* be1 = (const float*)d_in[4];
    const float* We2 = (const float*)d_in[5];
    const float* be2 = (const float*)d_in[6];
    const float* Wu1 = (const float*)d_in[7];
    const float* bu1 = (const float*)d_in[8];
    const float* Wu2 = (const float*)d_in[9];
    const float* bu2 = (const float*)d_in[10];
    const float* eps = (const float*)d_in[11];
    float*       out = (float*)d_out;

    const int N = in_sizes[0] / D;
    const int E = in_sizes[1] / 2;
    const int* src = ei;
    const int* dst = ei + E;

    const int SMEM_BYTES = 16896 * 4;   // 67584 per CTA; 2 CTAs/SM = 135KB
    cudaFuncSetAttribute(fused_mlp_mma<true>,  cudaFuncAttributeMaxDynamicSharedMemorySize, SMEM_BYTES);
    cudaFuncSetAttribute(fused_mlp_mma<false>, cudaFuncAttributeMaxDynamicSharedMemorySize, SMEM_BYTES);

    prep_weights<<<64, 256>>>(We1, We2, Wu1, Wu2);
    zero_agg<<<1024, 256>>>((size_t)N * D);

    int eblocks = (E + TILE - 1) / TILE;
    fused_mlp_mma<true><<<eblocks, NTHR, SMEM_BYTES>>>(x, src, dst, ea, be1, be2, eps, out, E);

    int nblocks = (N + TILE - 1) / TILE;
    fused_mlp_mma<false><<<nblocks, NTHR, SMEM_BYTES>>>(x, src, dst, ea, bu1, bu2, eps, out, N);
}

// round 14
// speedup vs baseline: 1.0734x; 1.0734x over previous
#include <cuda_runtime.h>
#include <cuda_fp16.h>
#include <math.h>
#include <stdint.h>

#define D      128
#define TILE   64
#define NTHR   256
#define MAXN   51200

// ---------------------------------------------------------------------------
// Static device scratch (no cudaMalloc allowed)
// ---------------------------------------------------------------------------
__device__ float    g_agg[(size_t)MAXN * D];   // scatter-add target
__device__ uint32_t g_Bh[4][8192];             // fp16 W images, uint4-packed frag order
// 0 = We1, 1 = We2, 2 = Wu1, 3 = Wu2  (32 KB each)

__device__ __forceinline__ uint32_t h2pack(float lo, float hi) {
    __half2 h = __floats2half2_rn(lo, hi);
    return *reinterpret_cast<uint32_t*>(&h);
}

__device__ __forceinline__ float gelu_exact(float v) {
    return 0.5f * v * (1.0f + erff(v * 0.70710678118654752f));
}

__device__ __forceinline__ void mma_f16(float* c,
                                        uint32_t a0, uint32_t a1, uint32_t a2, uint32_t a3,
                                        uint32_t b0, uint32_t b1) {
    asm volatile(
        "mma.sync.aligned.m16n8k16.row.col.f32.f16.f16.f32 "
        "{%0,%1,%2,%3}, {%4,%5,%6,%7}, {%8,%9}, {%0,%1,%2,%3};"
        : "+f"(c[0]), "+f"(c[1]), "+f"(c[2]), "+f"(c[3])
        : "r"(a0), "r"(a1), "r"(a2), "r"(a3), "r"(b0), "r"(b1));
}

__device__ __forceinline__ void red_add_v4(float* p, float4 v) {
    asm volatile("red.global.add.v4.f32 [%0], {%1,%2,%3,%4};"
                 :: "l"(p), "f"(v.x), "f"(v.y), "f"(v.z), "f"(v.w) : "memory");
}

// ---------------------------------------------------------------------------
// prep: W[k][n] -> fp16 m16n8k16 B-fragment order, uint4-packed.
// ---------------------------------------------------------------------------
__global__ void prep_weights(const float* __restrict__ We1, const float* __restrict__ We2,
                             const float* __restrict__ Wu1, const float* __restrict__ Wu2)
{
    int id = blockIdx.x * blockDim.x + threadIdx.x;
    if (id >= 4 * 4096) return;
    int m = id >> 12, r = id & 4095;
    int ca = r >> 8, s = (r >> 5) & 7, lane = r & 31;
    int g = lane >> 2, t = lane & 3;
    const float* W = (m == 0) ? We1 : (m == 1) ? We2 : (m == 2) ? Wu1 : Wu2;
    int n = ca * 8 + g;
    int k0 = 16 * s + 2 * t;
    uint32_t b0 = h2pack(W[k0 * D + n],       W[(k0 + 1) * D + n]);
    uint32_t b1 = h2pack(W[(k0 + 8) * D + n], W[(k0 + 9) * D + n]);
    int idx = ((ca * 4 + (s >> 1)) * 32 + lane) * 4 + (s & 1) * 2;
    g_Bh[m][idx]     = b0;
    g_Bh[m][idx + 1] = b1;
}

__global__ void zero_agg(size_t nd)
{
    size_t i = ((size_t)blockIdx.x * blockDim.x + threadIdx.x) * 4;
    size_t stride = (size_t)gridDim.x * blockDim.x * 4;
    float4 z = make_float4(0.f, 0.f, 0.f, 0.f);
    for (; i < nd; i += stride) *(float4*)(g_agg + i) = z;
}

// ---------------------------------------------------------------------------
// 32(rows)x32(cols)x128 GEMM slice per warp (fp16, m16n8k16);
// A fragment-major smem (LDS.128), B uint4 frags from L1-resident global.
// ra0 = row-group*2; Bq = image_u4 + wn*512 + lane.
// ---------------------------------------------------------------------------
__device__ __forceinline__ void do_gemm(const uint4* __restrict__ F,
                                        const uint4* __restrict__ Bq,
                                        int ra0, int lane,
                                        float acc[2][4][4])
{
    #pragma unroll
    for (int r = 0; r < 2; ++r)
        #pragma unroll
        for (int ca = 0; ca < 4; ++ca)
            #pragma unroll
            for (int q = 0; q < 4; ++q) acc[r][ca][q] = 0.f;

    #pragma unroll
    for (int sp = 0; sp < 4; ++sp) {
        int s0 = sp * 2, s1 = s0 + 1;
        uint4 a0[2], a1[2];
        #pragma unroll
        for (int r = 0; r < 2; ++r) {
            a0[r] = F[((ra0 + r) * 8 + s0) * 33 + lane];
            a1[r] = F[((ra0 + r) * 8 + s1) * 33 + lane];
        }
        #pragma unroll
        for (int ca = 0; ca < 4; ++ca) {
            uint4 b = __ldg(Bq + (ca * 4 + sp) * 32);
            #pragma unroll
            for (int r = 0; r < 2; ++r) {
                mma_f16(acc[r][ca], a0[r].x, a0[r].y, a0[r].z, a0[r].w, b.x, b.y);
                mma_f16(acc[r][ca], a1[r].x, a1[r].y, a1[r].z, a1[r].w, b.z, b.w);
            }
        }
    }
}

// ---------------------------------------------------------------------------
// Fused 2-layer MLP on a 64-row tile (fp16 MMA). 8 warps: 2 row-groups
// (32 rows) x 4 col-groups (32 cols); acc = 32 regs -> 64-reg budget ->
// 4 CTAs x 256 thr per SM. smem/CTA = 33.8KB (A frags + H frags, overlaid
// by the 64x132 fp32 linear epilogue region). 4-way cross-CTA phase overlap.
// ---------------------------------------------------------------------------
template <bool EDGE>
__global__ void __launch_bounds__(NTHR, 4) fused_mlp_mma(
    const float* __restrict__ x,
    const int*   __restrict__ src,
    const int*   __restrict__ dst,
    const float* __restrict__ ea,
    const float* __restrict__ b1,
    const float* __restrict__ b2,
    const float* __restrict__ eps,
    float*       __restrict__ out,
    int count)
{
    extern __shared__ float Asf[];                 // 8448 floats = 2112 uint4
    uint4* As4 = (uint4*)Asf;                      // A frags: [0, 1056)
    uint4* Hs4 = As4 + 1056;                       // H frags: [1056, 2112)

    const int tid  = threadIdx.x;
    const int lane = tid & 31, wid = tid >> 5;
    const int wm = wid & 1, wn = wid >> 1;         // 2 row-groups x 4 col-groups
    const int g = lane >> 2, t = lane & 3;
    const int r0 = blockIdx.x * TILE;
    const int imgbase = EDGE ? 0 : 2;

    // ---- gather: thread (atom = tid>>6 in 0..3, g_g = (tid>>3)&7, s = tid&7)
    //      handles rows (atom*16+g_g, +8), cols [16s, 16s+16) ----
    {
        const int atom = tid >> 6;
        const int g_g  = (tid >> 3) & 7;
        const int s    = tid & 7;
        const int rowA = r0 + atom * 16 + g_g, rowB = rowA + 8;
        const bool vA = rowA < count, vB = rowB < count;

        const float *pxA = nullptr, *peA = nullptr, *pxB = nullptr, *peB = nullptr;
        float oe = 0.f;
        if (EDGE) {
            if (vA) { pxA = x + (size_t)__ldg(&src[rowA]) * D; peA = ea + (size_t)rowA * D; }
            if (vB) { pxB = x + (size_t)__ldg(&src[rowB]) * D; peB = ea + (size_t)rowB * D; }
        } else {
            oe = 1.0f + eps[0];
            if (vA) { pxA = x + (size_t)rowA * D; peA = g_agg + (size_t)rowA * D; }
            if (vB) { pxB = x + (size_t)rowB * D; peB = g_agg + (size_t)rowB * D; }
        }

        float vAr[16], vBr[16];
        #pragma unroll
        for (int i = 0; i < 16; ++i) { vAr[i] = 0.f; vBr[i] = 0.f; }
        if (vA) {
            #pragma unroll
            for (int c = 0; c < 4; ++c) {
                float4 xa  = __ldg((const float4*)(pxA + s * 16 + c * 4));
                float4 eaa = __ldg((const float4*)(peA + s * 16 + c * 4));
                if (EDGE) {
                    vAr[c*4+0] = xa.x + eaa.x; vAr[c*4+1] = xa.y + eaa.y;
                    vAr[c*4+2] = xa.z + eaa.z; vAr[c*4+3] = xa.w + eaa.w;
                } else {
                    vAr[c*4+0] = fmaf(oe, xa.x, eaa.x); vAr[c*4+1] = fmaf(oe, xa.y, eaa.y);
                    vAr[c*4+2] = fmaf(oe, xa.z, eaa.z); vAr[c*4+3] = fmaf(oe, xa.w, eaa.w);
                }
            }
        }
        if (vB) {
            #pragma unroll
            for (int c = 0; c < 4; ++c) {
                float4 xa  = __ldg((const float4*)(pxB + s * 16 + c * 4));
                float4 eaa = __ldg((const float4*)(peB + s * 16 + c * 4));
                if (EDGE) {
                    vBr[c*4+0] = xa.x + eaa.x; vBr[c*4+1] = xa.y + eaa.y;
                    vBr[c*4+2] = xa.z + eaa.z; vBr[c*4+3] = xa.w + eaa.w;
                } else {
                    vBr[c*4+0] = fmaf(oe, xa.x, eaa.x); vBr[c*4+1] = fmaf(oe, xa.y, eaa.y);
                    vBr[c*4+2] = fmaf(oe, xa.z, eaa.z); vBr[c*4+3] = fmaf(oe, xa.w, eaa.w);
                }
            }
        }
        uint32_t base = (uint32_t)(atom * 8 + s) * 33 + g_g * 4;
        #pragma unroll
        for (int tt = 0; tt < 4; ++tt) {
            As4[base + tt] = make_uint4(
                h2pack(vAr[2*tt],     vAr[2*tt + 1]),
                h2pack(vBr[2*tt],     vBr[2*tt + 1]),
                h2pack(vAr[8 + 2*tt], vAr[9 + 2*tt]),
                h2pack(vBr[8 + 2*tt], vBr[9 + 2*tt]));
        }
    }
    __syncthreads();

    const uint4* Bq1 = (const uint4*)&g_Bh[imgbase][0]     + wn * 512 + lane;
    const uint4* Bq2 = (const uint4*)&g_Bh[imgbase + 1][0] + wn * 512 + lane;
    const int ra0 = wm * 2;

    float acc[2][4][4];

    // ---- GEMM1 (reads As4) ----
    do_gemm(As4, Bq1, ra0, lane, acc);
    // NO sync: H goes to its own buffer.

    // ---- epilogue1: H = GELU(C + b1) -> Hs4 ----
    #pragma unroll
    for (int p = 0; p < 2; ++p) {
        int sH = wn * 2 + p;
        int ca0 = 2 * p, ca1 = 2 * p + 1;
        int cb0 = wn * 32 + ca0 * 8 + 2 * t;
        int cb1 = wn * 32 + ca1 * 8 + 2 * t;
        float b00 = __ldg(&b1[cb0]), b01 = __ldg(&b1[cb0 + 1]);
        float b10 = __ldg(&b1[cb1]), b11 = __ldg(&b1[cb1 + 1]);
        #pragma unroll
        for (int ma = 0; ma < 2; ++ma) {
            uint4 f;
            f.x = h2pack(gelu_exact(acc[ma][ca0][0] + b00), gelu_exact(acc[ma][ca0][1] + b01));
            f.y = h2pack(gelu_exact(acc[ma][ca0][2] + b00), gelu_exact(acc[ma][ca0][3] + b01));
            f.z = h2pack(gelu_exact(acc[ma][ca1][0] + b10), gelu_exact(acc[ma][ca1][1] + b11));
            f.w = h2pack(gelu_exact(acc[ma][ca1][2] + b10), gelu_exact(acc[ma][ca1][3] + b11));
            Hs4[((ra0 + ma) * 8 + sH) * 33 + lane] = f;
        }
    }
    __syncthreads();

    // ---- GEMM2 (reads Hs4) ----
    do_gemm(Hs4, Bq2, ra0, lane, acc);
    __syncthreads();     // H reads complete before linear overlay writes

    // ---- epilogue2: raw C2 -> linear smem (fp32 overlays frag buffers) ----
    #pragma unroll
    for (int ca = 0; ca < 4; ++ca) {
        int col = wn * 32 + ca * 8 + 2 * t;
        #pragma unroll
        for (int ma = 0; ma < 2; ++ma) {
            int row = wm * 32 + ma * 16 + g;
            *(float2*)(Asf + row * 132 + col)       = make_float2(acc[ma][ca][0], acc[ma][ca][1]);
            *(float2*)(Asf + (row + 8) * 132 + col) = make_float2(acc[ma][ca][2], acc[ma][ca][3]);
        }
    }
    __syncthreads();

    // ---- output: coalesced + bias; edge -> red.v4 scatter, node -> store ----
    {
        int c4 = lane * 4;
        float4 bias = *(const float4*)&b2[c4];
        int rbase = wid * 8;
        #pragma unroll
        for (int i = 0; i < 8; ++i) {
            int r = rbase + i;
            int row = r0 + r;
            if (row < count) {
                float4 v = *(float4*)(Asf + r * 132 + c4);
                v.x += bias.x; v.y += bias.y; v.z += bias.z; v.w += bias.w;
                if (EDGE) {
                    int dn = __ldg(&dst[row]);
                    red_add_v4(g_agg + (size_t)dn * D + c4, v);
                } else {
                    *(float4*)(out + (size_t)row * D + c4) = v;
                }
            }
        }
    }
}

// ---------------------------------------------------------------------------
// Inputs: x, edge_index(int32 [2,E]), edge_attr, We1, be1, We2, be2,
//         Wu1, bu1, Wu2, bu2, eps
// ---------------------------------------------------------------------------
extern "C" void kernel_launch(void* const* d_in, const int* in_sizes, int n_in,
                              void* d_out, int out_size)
{
    const float* x   = (const float*)d_in[0];
    const int*   ei  = (const int*)d_in[1];
    const float* ea  = (const float*)d_in[2];
    const float* We1 = (const float*)d_in[3];
    const float* be1 = (const float*)d_in[4];
    const float* We2 = (const float*)d_in[5];
    const float* be2 = (const float*)d_in[6];
    const float* Wu1 = (const float*)d_in[7];
    const float* bu1 = (const float*)d_in[8];
    const float* Wu2 = (const float*)d_in[9];
    const float* bu2 = (const float*)d_in[10];
    const float* eps = (const float*)d_in[11];
    float*       out = (float*)d_out;

    const int N = in_sizes[0] / D;
    const int E = in_sizes[1] / 2;
    const int* src = ei;
    const int* dst = ei + E;

    const int SMEM_BYTES = 2112 * 16;   // 33792 per CTA; 4 CTAs/SM = 135KB
    cudaFuncSetAttribute(fused_mlp_mma<true>,  cudaFuncAttributeMaxDynamicSharedMemorySize, SMEM_BYTES);
    cudaFuncSetAttribute(fused_mlp_mma<false>, cudaFuncAttributeMaxDynamicSharedMemorySize, SMEM_BYTES);

    prep_weights<<<64, 256>>>(We1, We2, Wu1, Wu2);
    zero_agg<<<1024, 256>>>((size_t)N * D);

    int eblocks = (E + TILE - 1) / TILE;
    fused_mlp_mma<true><<<eblocks, NTHR, SMEM_BYTES>>>(x, src, dst, ea, be1, be2, eps, out, E);

    int nblocks = (N + TILE - 1) / TILE;
    fused_mlp_mma<false><<<nblocks, NTHR, SMEM_BYTES>>>(x, src, dst, ea, bu1, bu2, eps, out, N);
}

// round 15
// speedup vs baseline: 1.1136x; 1.0375x over previous
#include <cuda_runtime.h>
#include <cuda_fp16.h>
#include <math.h>
#include <stdint.h>

#define D      128
#define TILE   128
#define NTHR   256
#define MAXN   51200

// ---------------------------------------------------------------------------
// Static device scratch (no cudaMalloc allowed)
// ---------------------------------------------------------------------------
__device__ float    g_agg[(size_t)MAXN * D];   // scatter-add target
__device__ uint32_t g_Bh[4][8192];             // fp16 W images, uint4-packed frag order
// 0 = We1, 1 = We2, 2 = Wu1, 3 = Wu2  (32 KB each)

__device__ __forceinline__ uint32_t h2pack(float lo, float hi) {
    __half2 h = __floats2half2_rn(lo, hi);
    return *reinterpret_cast<uint32_t*>(&h);
}

__device__ __forceinline__ float gelu_exact(float v) {
    return 0.5f * v * (1.0f + erff(v * 0.70710678118654752f));
}

// streaming load: do NOT allocate in L1 (protects x rows + B images in L1)
__device__ __forceinline__ float4 ldg_stream(const float4* p) {
    float4 v;
    asm("ld.global.nc.L1::no_allocate.v4.f32 {%0,%1,%2,%3}, [%4];"
        : "=f"(v.x), "=f"(v.y), "=f"(v.z), "=f"(v.w) : "l"(p));
    return v;
}

__device__ __forceinline__ void mma_f16(float* c,
                                        uint32_t a0, uint32_t a1, uint32_t a2, uint32_t a3,
                                        uint32_t b0, uint32_t b1) {
    asm volatile(
        "mma.sync.aligned.m16n8k16.row.col.f32.f16.f16.f32 "
        "{%0,%1,%2,%3}, {%4,%5,%6,%7}, {%8,%9}, {%0,%1,%2,%3};"
        : "+f"(c[0]), "+f"(c[1]), "+f"(c[2]), "+f"(c[3])
        : "r"(a0), "r"(a1), "r"(a2), "r"(a3), "r"(b0), "r"(b1));
}

__device__ __forceinline__ void red_add_v4(float* p, float4 v) {
    asm volatile("red.global.add.v4.f32 [%0], {%1,%2,%3,%4};"
                 :: "l"(p), "f"(v.x), "f"(v.y), "f"(v.z), "f"(v.w) : "memory");
}

// ---------------------------------------------------------------------------
// prep: W[k][n] -> fp16 m16n8k16 B-fragment order, uint4-packed.
// ---------------------------------------------------------------------------
__global__ void prep_weights(const float* __restrict__ We1, const float* __restrict__ We2,
                             const float* __restrict__ Wu1, const float* __restrict__ Wu2)
{
    int id = blockIdx.x * blockDim.x + threadIdx.x;
    if (id >= 4 * 4096) return;
    int m = id >> 12, r = id & 4095;
    int ca = r >> 8, s = (r >> 5) & 7, lane = r & 31;
    int g = lane >> 2, t = lane & 3;
    const float* W = (m == 0) ? We1 : (m == 1) ? We2 : (m == 2) ? Wu1 : Wu2;
    int n = ca * 8 + g;
    int k0 = 16 * s + 2 * t;
    uint32_t b0 = h2pack(W[k0 * D + n],       W[(k0 + 1) * D + n]);
    uint32_t b1 = h2pack(W[(k0 + 8) * D + n], W[(k0 + 9) * D + n]);
    int idx = ((ca * 4 + (s >> 1)) * 32 + lane) * 4 + (s & 1) * 2;
    g_Bh[m][idx]     = b0;
    g_Bh[m][idx + 1] = b1;
}

__global__ void zero_agg(size_t nd)
{
    size_t i = ((size_t)blockIdx.x * blockDim.x + threadIdx.x) * 4;
    size_t stride = (size_t)gridDim.x * blockDim.x * 4;
    float4 z = make_float4(0.f, 0.f, 0.f, 0.f);
    for (; i < nd; i += stride) *(float4*)(g_agg + i) = z;
}

// dummy: shifts ncu's capture slot so the EDGE kernel lands at -s 5
__global__ void slot_pad() {}

// ---------------------------------------------------------------------------
// 64(rows)x32(cols)x128 GEMM slice per warp (fp16, m16n8k16);
// A fragment-major smem (LDS.128), B uint4 frags from L1-resident global.
// ---------------------------------------------------------------------------
__device__ __forceinline__ void do_gemm(const uint4* __restrict__ F,
                                        const uint4* __restrict__ Bq,
                                        int ra0, int lane,
                                        float acc[4][4][4])
{
    #pragma unroll
    for (int r = 0; r < 4; ++r)
        #pragma unroll
        for (int ca = 0; ca < 4; ++ca)
            #pragma unroll
            for (int q = 0; q < 4; ++q) acc[r][ca][q] = 0.f;

    #pragma unroll
    for (int sp = 0; sp < 4; ++sp) {
        int s0 = sp * 2, s1 = s0 + 1;
        uint4 a0[4], a1[4];
        #pragma unroll
        for (int r = 0; r < 4; ++r) {
            a0[r] = F[((ra0 + r) * 8 + s0) * 33 + lane];
            a1[r] = F[((ra0 + r) * 8 + s1) * 33 + lane];
        }
        #pragma unroll
        for (int ca = 0; ca < 4; ++ca) {
            uint4 b = __ldg(Bq + (ca * 4 + sp) * 32);
            #pragma unroll
            for (int r = 0; r < 4; ++r) {
                mma_f16(acc[r][ca], a0[r].x, a0[r].y, a0[r].z, a0[r].w, b.x, b.y);
                mma_f16(acc[r][ca], a1[r].x, a1[r].y, a1[r].z, a1[r].w, b.z, b.w);
            }
        }
    }
}

// ---------------------------------------------------------------------------
// Fused 2-layer MLP on a 128-row tile (fp16 MMA). 8 warps: 2 row-groups x
// 4 col-groups. smem = 67.6KB tile buffer -> 2 CTAs/SM; B images in L1.
// Streaming arrays (ea / g_agg-read) bypass L1 (no_allocate).
// EDGE: A = x[src]+ea -> MLP -> smem-recoalesced red.v4 into g_agg[dst]
// NODE: A = (1+eps)*x + g_agg -> MLP -> out
// ---------------------------------------------------------------------------
template <bool EDGE>
__global__ void __launch_bounds__(NTHR, 2) fused_mlp_mma(
    const float* __restrict__ x,
    const int*   __restrict__ src,
    const int*   __restrict__ dst,
    const float* __restrict__ ea,
    const float* __restrict__ b1,
    const float* __restrict__ b2,
    const float* __restrict__ eps,
    float*       __restrict__ out,
    int count)
{
    extern __shared__ float Asf[];                 // 16896 floats = 4224 uint4
    uint4* As4 = (uint4*)Asf;

    const int tid  = threadIdx.x;
    const int lane = tid & 31, wid = tid >> 5;
    const int wm = wid & 1, wn = wid >> 1;         // 2 row-groups x 4 col-groups
    const int g = lane >> 2, t = lane & 3;
    const int r0 = blockIdx.x * TILE;
    const int imgbase = EDGE ? 0 : 2;

    // ---- gather: thread handles rows (ra*16+g_g, +8), ksteps s in {q, q+4} ----
    {
        const int pr = tid >> 2;
        const int ra_g = pr >> 3, g_g = pr & 7;
        const int rowA = r0 + ra_g * 16 + g_g, rowB = rowA + 8;
        const bool vA = rowA < count, vB = rowB < count;

        const float *pxA = nullptr, *peA = nullptr, *pxB = nullptr, *peB = nullptr;
        float oe = 0.f;
        if (EDGE) {
            if (vA) { pxA = x + (size_t)__ldg(&src[rowA]) * D; peA = ea + (size_t)rowA * D; }
            if (vB) { pxB = x + (size_t)__ldg(&src[rowB]) * D; peB = ea + (size_t)rowB * D; }
        } else {
            oe = 1.0f + eps[0];
            if (vA) { pxA = x + (size_t)rowA * D; peA = g_agg + (size_t)rowA * D; }
            if (vB) { pxB = x + (size_t)rowB * D; peB = g_agg + (size_t)rowB * D; }
        }

        #pragma unroll
        for (int half = 0; half < 2; ++half) {
            int s = (tid & 3) + half * 4;
            float vAr[16], vBr[16];
            #pragma unroll
            for (int i = 0; i < 16; ++i) { vAr[i] = 0.f; vBr[i] = 0.f; }
            if (vA) {
                #pragma unroll
                for (int c = 0; c < 4; ++c) {
                    float4 xa  = __ldg((const float4*)(pxA + s * 16 + c * 4));
                    float4 eaa = ldg_stream((const float4*)(peA + s * 16 + c * 4));
                    if (EDGE) {
                        vAr[c*4+0] = xa.x + eaa.x; vAr[c*4+1] = xa.y + eaa.y;
                        vAr[c*4+2] = xa.z + eaa.z; vAr[c*4+3] = xa.w + eaa.w;
                    } else {
                        vAr[c*4+0] = fmaf(oe, xa.x, eaa.x); vAr[c*4+1] = fmaf(oe, xa.y, eaa.y);
                        vAr[c*4+2] = fmaf(oe, xa.z, eaa.z); vAr[c*4+3] = fmaf(oe, xa.w, eaa.w);
                    }
                }
            }
            if (vB) {
                #pragma unroll
                for (int c = 0; c < 4; ++c) {
                    float4 xa  = __ldg((const float4*)(pxB + s * 16 + c * 4));
                    float4 eaa = ldg_stream((const float4*)(peB + s * 16 + c * 4));
                    if (EDGE) {
                        vBr[c*4+0] = xa.x + eaa.x; vBr[c*4+1] = xa.y + eaa.y;
                        vBr[c*4+2] = xa.z + eaa.z; vBr[c*4+3] = xa.w + eaa.w;
                    } else {
                        vBr[c*4+0] = fmaf(oe, xa.x, eaa.x); vBr[c*4+1] = fmaf(oe, xa.y, eaa.y);
                        vBr[c*4+2] = fmaf(oe, xa.z, eaa.z); vBr[c*4+3] = fmaf(oe, xa.w, eaa.w);
                    }
                }
            }
            uint32_t base = (uint32_t)(ra_g * 8 + s) * 33 + g_g * 4;
            #pragma unroll
            for (int tt = 0; tt < 4; ++tt) {
                As4[base + tt] = make_uint4(
                    h2pack(vAr[2*tt],     vAr[2*tt + 1]),
                    h2pack(vBr[2*tt],     vBr[2*tt + 1]),
                    h2pack(vAr[8 + 2*tt], vAr[9 + 2*tt]),
                    h2pack(vBr[8 + 2*tt], vBr[9 + 2*tt]));
            }
        }
    }
    __syncthreads();

    const uint4* Bq1 = (const uint4*)&g_Bh[imgbase][0]     + wn * 512 + lane;
    const uint4* Bq2 = (const uint4*)&g_Bh[imgbase + 1][0] + wn * 512 + lane;
    const int ra0 = wm * 4;

    float acc[4][4][4];

    // ---- GEMM1 ----
    do_gemm(As4, Bq1, ra0, lane, acc);
    __syncthreads();

    // ---- epilogue1: H = GELU(C + b1) -> fp16 A-frag smem ----
    #pragma unroll
    for (int p = 0; p < 2; ++p) {
        int sH = wn * 2 + p;
        int ca0 = 2 * p, ca1 = 2 * p + 1;
        int cb0 = wn * 32 + ca0 * 8 + 2 * t;
        int cb1 = wn * 32 + ca1 * 8 + 2 * t;
        float b00 = __ldg(&b1[cb0]), b01 = __ldg(&b1[cb0 + 1]);
        float b10 = __ldg(&b1[cb1]), b11 = __ldg(&b1[cb1 + 1]);
        #pragma unroll
        for (int ma = 0; ma < 4; ++ma) {
            uint4 f;
            f.x = h2pack(gelu_exact(acc[ma][ca0][0] + b00), gelu_exact(acc[ma][ca0][1] + b01));
            f.y = h2pack(gelu_exact(acc[ma][ca0][2] + b00), gelu_exact(acc[ma][ca0][3] + b01));
            f.z = h2pack(gelu_exact(acc[ma][ca1][0] + b10), gelu_exact(acc[ma][ca1][1] + b11));
            f.w = h2pack(gelu_exact(acc[ma][ca1][2] + b10), gelu_exact(acc[ma][ca1][3] + b11));
            As4[((ra0 + ma) * 8 + sH) * 33 + lane] = f;
        }
    }
    __syncthreads();

    // ---- GEMM2 ----
    do_gemm(As4, Bq2, ra0, lane, acc);
    __syncthreads();

    // ---- epilogue2: raw C2 -> linear smem (fp32) ----
    #pragma unroll
    for (int ca = 0; ca < 4; ++ca) {
        int col = wn * 32 + ca * 8 + 2 * t;
        #pragma unroll
        for (int ma = 0; ma < 4; ++ma) {
            int row = wm * 64 + ma * 16 + g;
            *(float2*)(Asf + row * 132 + col)       = make_float2(acc[ma][ca][0], acc[ma][ca][1]);
            *(float2*)(Asf + (row + 8) * 132 + col) = make_float2(acc[ma][ca][2], acc[ma][ca][3]);
        }
    }
    __syncthreads();

    // ---- output: coalesced + bias; edge -> red.v4 scatter, node -> store ----
    {
        int c4 = lane * 4;
        float4 bias = *(const float4*)&b2[c4];
        int rbase = wid * 16;
        #pragma unroll
        for (int i = 0; i < 16; ++i) {
            int r = rbase + i;
            int row = r0 + r;
            if (row < count) {
                float4 v = *(float4*)(Asf + r * 132 + c4);
                v.x += bias.x; v.y += bias.y; v.z += bias.z; v.w += bias.w;
                if (EDGE) {
                    int dn = __ldg(&dst[row]);
                    red_add_v4(g_agg + (size_t)dn * D + c4, v);
                } else {
                    *(float4*)(out + (size_t)row * D + c4) = v;
                }
            }
        }
    }
}

// ---------------------------------------------------------------------------
// Inputs: x, edge_index(int32 [2,E]), edge_attr, We1, be1, We2, be2,
//         Wu1, bu1, Wu2, bu2, eps
// ---------------------------------------------------------------------------
extern "C" void kernel_launch(void* const* d_in, const int* in_sizes, int n_in,
                              void* d_out, int out_size)
{
    const float* x   = (const float*)d_in[0];
    const int*   ei  = (const int*)d_in[1];
    const float* ea  = (const float*)d_in[2];
    const float* We1 = (const float*)d_in[3];
    const float* be1 = (const float*)d_in[4];
    const float* We2 = (const float*)d_in[5];
    const float* be2 = (const float*)d_in[6];
    const float* Wu1 = (const float*)d_in[7];
    const float* bu1 = (const float*)d_in[8];
    const float* Wu2 = (const float*)d_in[9];
    const float* bu2 = (const float*)d_in[10];
    const float* eps = (const float*)d_in[11];
    float*       out = (float*)d_out;

    const int N = in_sizes[0] / D;
    const int E = in_sizes[1] / 2;
    const int* src = ei;
    const int* dst = ei + E;

    const int SMEM_BYTES = 16896 * 4;   // 67584 — tile buffer => 2 CTAs/SM
    cudaFuncSetAttribute(fused_mlp_mma<true>,  cudaFuncAttributeMaxDynamicSharedMemorySize, SMEM_BYTES);
    cudaFuncSetAttribute(fused_mlp_mma<false>, cudaFuncAttributeMaxDynamicSharedMemorySize, SMEM_BYTES);

    prep_weights<<<64, 256>>>(We1, We2, Wu1, Wu2);
    zero_agg<<<1024, 256>>>((size_t)N * D);
    slot_pad<<<1, 32>>>();   // shifts ncu -s 5 capture onto the edge kernel

    int eblocks = (E + TILE - 1) / TILE;
    fused_mlp_mma<true><<<eblocks, NTHR, SMEM_BYTES>>>(x, src, dst, ea, be1, be2, eps, out, E);

    int nblocks = (N + TILE - 1) / TILE;
    fused_mlp_mma<false><<<nblocks, NTHR, SMEM_BYTES>>>(x, src, dst, ea, bu1, bu2, eps, out, N);
}

// round 16
// speedup vs baseline: 1.1374x; 1.0213x over previous
#include <cuda_runtime.h>
#include <cuda_fp16.h>
#include <math.h>
#include <stdint.h>

#define D      128
#define TILE   128
#define NTHR   256
#define MAXN   51200

// ---------------------------------------------------------------------------
// Static device scratch (no cudaMalloc allowed)
// ---------------------------------------------------------------------------
__device__ float    g_agg[(size_t)MAXN * D];   // scatter-add target
__device__ uint32_t g_Bh[4][8192];             // fp16 W images, uint4-packed frag order
// 0 = We1, 1 = We2, 2 = Wu1, 3 = Wu2  (32 KB each)

__device__ __forceinline__ uint32_t h2pack(float lo, float hi) {
    __half2 h = __floats2half2_rn(lo, hi);
    return *reinterpret_cast<uint32_t*>(&h);
}

__device__ __forceinline__ float gelu_exact(float v) {
    return 0.5f * v * (1.0f + erff(v * 0.70710678118654752f));
}

// streaming load: do NOT allocate in L1 (protects x rows + B images in L1)
__device__ __forceinline__ float4 ldg_stream(const float4* p) {
    float4 v;
    asm("ld.global.nc.L1::no_allocate.v4.f32 {%0,%1,%2,%3}, [%4];"
        : "=f"(v.x), "=f"(v.y), "=f"(v.z), "=f"(v.w) : "l"(p));
    return v;
}

__device__ __forceinline__ void mma_f16(float* c,
                                        uint32_t a0, uint32_t a1, uint32_t a2, uint32_t a3,
                                        uint32_t b0, uint32_t b1) {
    asm volatile(
        "mma.sync.aligned.m16n8k16.row.col.f32.f16.f16.f32 "
        "{%0,%1,%2,%3}, {%4,%5,%6,%7}, {%8,%9}, {%0,%1,%2,%3};"
        : "+f"(c[0]), "+f"(c[1]), "+f"(c[2]), "+f"(c[3])
        : "r"(a0), "r"(a1), "r"(a2), "r"(a3), "r"(b0), "r"(b1));
}

__device__ __forceinline__ void red_add_v4(float* p, float4 v) {
    asm volatile("red.global.add.v4.f32 [%0], {%1,%2,%3,%4};"
                 :: "l"(p), "f"(v.x), "f"(v.y), "f"(v.z), "f"(v.w) : "memory");
}

// ---------------------------------------------------------------------------
// prep: W[k][n] -> fp16 m16n8k16 B-fragment order, uint4-packed.
// ---------------------------------------------------------------------------
__global__ void prep_weights(const float* __restrict__ We1, const float* __restrict__ We2,
                             const float* __restrict__ Wu1, const float* __restrict__ Wu2)
{
    int id = blockIdx.x * blockDim.x + threadIdx.x;
    if (id >= 4 * 4096) return;
    int m = id >> 12, r = id & 4095;
    int ca = r >> 8, s = (r >> 5) & 7, lane = r & 31;
    int g = lane >> 2, t = lane & 3;
    const float* W = (m == 0) ? We1 : (m == 1) ? We2 : (m == 2) ? Wu1 : Wu2;
    int n = ca * 8 + g;
    int k0 = 16 * s + 2 * t;
    uint32_t b0 = h2pack(W[k0 * D + n],       W[(k0 + 1) * D + n]);
    uint32_t b1 = h2pack(W[(k0 + 8) * D + n], W[(k0 + 9) * D + n]);
    int idx = ((ca * 4 + (s >> 1)) * 32 + lane) * 4 + (s & 1) * 2;
    g_Bh[m][idx]     = b0;
    g_Bh[m][idx + 1] = b1;
}

__global__ void zero_agg(size_t nd)
{
    size_t i = ((size_t)blockIdx.x * blockDim.x + threadIdx.x) * 4;
    size_t stride = (size_t)gridDim.x * blockDim.x * 4;
    float4 z = make_float4(0.f, 0.f, 0.f, 0.f);
    for (; i < nd; i += stride) *(float4*)(g_agg + i) = z;
}

// dummy: keeps ncu's -s 5 capture on the EDGE kernel
__global__ void slot_pad() {}

// ---------------------------------------------------------------------------
// 64(rows)x32(cols)x128 GEMM slice per warp (fp16, m16n8k16);
// A fragment-major smem (LDS.128), B uint4 frags from L1-resident global.
// ---------------------------------------------------------------------------
__device__ __forceinline__ void do_gemm(const uint4* __restrict__ F,
                                        const uint4* __restrict__ Bq,
                                        int ra0, int lane,
                                        float acc[4][4][4])
{
    #pragma unroll
    for (int r = 0; r < 4; ++r)
        #pragma unroll
        for (int ca = 0; ca < 4; ++ca)
            #pragma unroll
            for (int q = 0; q < 4; ++q) acc[r][ca][q] = 0.f;

    #pragma unroll
    for (int sp = 0; sp < 4; ++sp) {
        int s0 = sp * 2, s1 = s0 + 1;
        uint4 a0[4], a1[4];
        #pragma unroll
        for (int r = 0; r < 4; ++r) {
            a0[r] = F[((ra0 + r) * 8 + s0) * 33 + lane];
            a1[r] = F[((ra0 + r) * 8 + s1) * 33 + lane];
        }
        #pragma unroll
        for (int ca = 0; ca < 4; ++ca) {
            uint4 b = __ldg(Bq + (ca * 4 + sp) * 32);
            #pragma unroll
            for (int r = 0; r < 4; ++r) {
                mma_f16(acc[r][ca], a0[r].x, a0[r].y, a0[r].z, a0[r].w, b.x, b.y);
                mma_f16(acc[r][ca], a1[r].x, a1[r].y, a1[r].z, a1[r].w, b.z, b.w);
            }
        }
    }
}

// ---------------------------------------------------------------------------
// Fused 2-layer MLP on a 128-row tile (fp16 MMA). 8 warps: 2 row-groups x
// 4 col-groups. smem = 67.6KB tile buffer -> 2 CTAs/SM; B images in L1.
// Gather restructured: each warp LDG.128 covers 4 rows x 128B contiguous
// (minimal 4 wavefronts/instr); fragments written via STS.32 pairs.
// EDGE: A = x[src]+ea -> MLP -> smem-recoalesced red.v4 into g_agg[dst]
// NODE: A = (1+eps)*x + g_agg -> MLP -> out
// ---------------------------------------------------------------------------
template <bool EDGE>
__global__ void __launch_bounds__(NTHR, 2) fused_mlp_mma(
    const float* __restrict__ x,
    const int*   __restrict__ src,
    const int*   __restrict__ dst,
    const float* __restrict__ ea,
    const float* __restrict__ b1,
    const float* __restrict__ b2,
    const float* __restrict__ eps,
    float*       __restrict__ out,
    int count)
{
    extern __shared__ float Asf[];                 // 16896 floats = 4224 uint4
    uint4*    As4  = (uint4*)Asf;
    uint32_t* As32 = (uint32_t*)Asf;

    const int tid  = threadIdx.x;
    const int lane = tid & 31, wid = tid >> 5;
    const int wm = wid & 1, wn = wid >> 1;         // 2 row-groups x 4 col-groups
    const int g = lane >> 2, t = lane & 3;
    const int r0 = blockIdx.x * TILE;
    const int imgbase = EDGE ? 0 : 2;

    // ---- gather (coalesced): warp instr = 4 rows x 128B contiguous ----
    {
        const int o   = lane & 7;          // 128B octant within row
        const int rg  = lane >> 3;         // row within warp's 4-row group
        const int kq  = o & 3, sb = o >> 2;
        const int aX2 = (kq >> 1) * 2;     // a2/a3 half selector *2
        const int t0  = (kq & 1) * 2;      // t of first pack (0 or 2)
        const float oe = EDGE ? 0.f : (1.0f + eps[0]);

        #pragma unroll
        for (int p = 0; p < 4; ++p) {
            const int lrow = wid * 4 + rg + 32 * p;   // 0..127
            const int row  = r0 + lrow;
            const bool v   = row < count;

            const float* px = nullptr;
            const float* pe = nullptr;
            if (EDGE) {
                if (v) { px = x + (size_t)__ldg(&src[row]) * D; pe = ea + (size_t)row * D; }
            } else {
                if (v) { px = x + (size_t)row * D; pe = g_agg + (size_t)row * D; }
            }
            const int atom = lrow >> 4, g_g = lrow & 7, rh = (lrow >> 3) & 1;

            #pragma unroll
            for (int c = 0; c < 4; ++c) {
                float f0 = 0.f, f1 = 0.f, f2 = 0.f, f3 = 0.f;
                if (v) {
                    int col = 32 * c + 4 * o;
                    float4 xa  = __ldg((const float4*)(px + col));
                    float4 eaa = ldg_stream((const float4*)(pe + col));
                    if (EDGE) {
                        f0 = xa.x + eaa.x; f1 = xa.y + eaa.y;
                        f2 = xa.z + eaa.z; f3 = xa.w + eaa.w;
                    } else {
                        f0 = fmaf(oe, xa.x, eaa.x); f1 = fmaf(oe, xa.y, eaa.y);
                        f2 = fmaf(oe, xa.z, eaa.z); f3 = fmaf(oe, xa.w, eaa.w);
                    }
                }
                int s = 2 * c + sb;
                uint32_t idx = (uint32_t)((atom * 8 + s) * 33 + g_g * 4 + t0) * 4 + aX2 + rh;
                As32[idx]     = h2pack(f0, f1);
                As32[idx + 4] = h2pack(f2, f3);
            }
        }
    }
    __syncthreads();

    const uint4* Bq1 = (const uint4*)&g_Bh[imgbase][0]     + wn * 512 + lane;
    const uint4* Bq2 = (const uint4*)&g_Bh[imgbase + 1][0] + wn * 512 + lane;
    const int ra0 = wm * 4;

    float acc[4][4][4];

    // ---- GEMM1 ----
    do_gemm(As4, Bq1, ra0, lane, acc);
    __syncthreads();

    // ---- epilogue1: H = GELU(C + b1) -> fp16 A-frag smem ----
    #pragma unroll
    for (int p = 0; p < 2; ++p) {
        int sH = wn * 2 + p;
        int ca0 = 2 * p, ca1 = 2 * p + 1;
        int cb0 = wn * 32 + ca0 * 8 + 2 * t;
        int cb1 = wn * 32 + ca1 * 8 + 2 * t;
        float b00 = __ldg(&b1[cb0]), b01 = __ldg(&b1[cb0 + 1]);
        float b10 = __ldg(&b1[cb1]), b11 = __ldg(&b1[cb1 + 1]);
        #pragma unroll
        for (int ma = 0; ma < 4; ++ma) {
            uint4 f;
            f.x = h2pack(gelu_exact(acc[ma][ca0][0] + b00), gelu_exact(acc[ma][ca0][1] + b01));
            f.y = h2pack(gelu_exact(acc[ma][ca0][2] + b00), gelu_exact(acc[ma][ca0][3] + b01));
            f.z = h2pack(gelu_exact(acc[ma][ca1][0] + b10), gelu_exact(acc[ma][ca1][1] + b11));
            f.w = h2pack(gelu_exact(acc[ma][ca1][2] + b10), gelu_exact(acc[ma][ca1][3] + b11));
            As4[((ra0 + ma) * 8 + sH) * 33 + lane] = f;
        }
    }
    __syncthreads();

    // ---- GEMM2 ----
    do_gemm(As4, Bq2, ra0, lane, acc);
    __syncthreads();

    // ---- epilogue2: raw C2 -> linear smem (fp32) ----
    #pragma unroll
    for (int ca = 0; ca < 4; ++ca) {
        int col = wn * 32 + ca * 8 + 2 * t;
        #pragma unroll
        for (int ma = 0; ma < 4; ++ma) {
            int row = wm * 64 + ma * 16 + g;
            *(float2*)(Asf + row * 132 + col)       = make_float2(acc[ma][ca][0], acc[ma][ca][1]);
            *(float2*)(Asf + (row + 8) * 132 + col) = make_float2(acc[ma][ca][2], acc[ma][ca][3]);
        }
    }
    __syncthreads();

    // ---- output: coalesced + bias; edge -> red.v4 scatter, node -> store ----
    {
        int c4 = lane * 4;
        float4 bias = *(const float4*)&b2[c4];
        int rbase = wid * 16;
        #pragma unroll
        for (int i = 0; i < 16; ++i) {
            int r = rbase + i;
            int row = r0 + r;
            if (row < count) {
                float4 v = *(float4*)(Asf + r * 132 + c4);
                v.x += bias.x; v.y += bias.y; v.z += bias.z; v.w += bias.w;
                if (EDGE) {
                    int dn = __ldg(&dst[row]);
                    red_add_v4(g_agg + (size_t)dn * D + c4, v);
                } else {
                    *(float4*)(out + (size_t)row * D + c4) = v;
                }
            }
        }
    }
}

// ---------------------------------------------------------------------------
// Inputs: x, edge_index(int32 [2,E]), edge_attr, We1, be1, We2, be2,
//         Wu1, bu1, Wu2, bu2, eps
// ---------------------------------------------------------------------------
extern "C" void kernel_launch(void* const* d_in, const int* in_sizes, int n_in,
                              void* d_out, int out_size)
{
    const float* x   = (const float*)d_in[0];
    const int*   ei  = (const int*)d_in[1];
    const float* ea  = (const float*)d_in[2];
    const float* We1 = (const float*)d_in[3];
    const float* be1 = (const float*)d_in[4];
    const float* We2 = (const float*)d_in[5];
    const float* be2 = (const float*)d_in[6];
    const float* Wu1 = (const float*)d_in[7];
    const float* bu1 = (const float*)d_in[8];
    const float* Wu2 = (const float*)d_in[9];
    const float* bu2 = (const float*)d_in[10];
    const float* eps = (const float*)d_in[11];
    float*       out = (float*)d_out;

    const int N = in_sizes[0] / D;
    const int E = in_sizes[1] / 2;
    const int* src = ei;
    const int* dst = ei + E;

    const int SMEM_BYTES = 16896 * 4;   // 67584 — tile buffer => 2 CTAs/SM
    cudaFuncSetAttribute(fused_mlp_mma<true>,  cudaFuncAttributeMaxDynamicSharedMemorySize, SMEM_BYTES);
    cudaFuncSetAttribute(fused_mlp_mma<false>, cudaFuncAttributeMaxDynamicSharedMemorySize, SMEM_BYTES);

    prep_weights<<<64, 256>>>(We1, We2, Wu1, Wu2);
    zero_agg<<<1024, 256>>>((size_t)N * D);
    slot_pad<<<1, 32>>>();   // keeps ncu -s 5 capture on the edge kernel

    int eblocks = (E + TILE - 1) / TILE;
    fused_mlp_mma<true><<<eblocks, NTHR, SMEM_BYTES>>>(x, src, dst, ea, be1, be2, eps, out, E);

    int nblocks = (N + TILE - 1) / TILE;
    fused_mlp_mma<false><<<nblocks, NTHR, SMEM_BYTES>>>(x, src, dst, ea, bu1, bu2, eps, out, N);
}